// round 1
// baseline (speedup 1.0000x reference)
#include <cuda_runtime.h>
#include <math_constants.h>

// ---------------------------------------------------------------------------
// Problem constants: B=4, S=1024, D=1024, H=16, DH=64, HID=4096
// Tokens TOK = B*S = 4096.
// ---------------------------------------------------------------------------
#define TOK   4096
#define DMODEL 1024
#define HIDDEN 4096

// ------------------------- scratch (__device__ globals) --------------------
__device__ float g_Q   [TOK * DMODEL];
__device__ float g_K   [TOK * DMODEL];
__device__ float g_V   [TOK * DMODEL];
__device__ float g_att [TOK * DMODEL];
__device__ float g_x1  [TOK * DMODEL];
__device__ float g_x2  [TOK * DMODEL];
__device__ float g_tmp [TOK * DMODEL];
__device__ float g_hid [(size_t)TOK * HIDDEN];

// ---------------------------------------------------------------------------
// Generic SGEMM: C[M,N] = A[M,K] @ B'[K,N] + bias[N]   (optional ReLU)
//   bmode 0: B is standard row-major [K, N]
//   bmode 1: B is per-head [H, K, 64]; logical col c -> (c>>6)*K*64 + k*64 + (c&63)
// 128x128 tile, BK=8, 256 threads, 8x8 microtile.
// ---------------------------------------------------------------------------
#define GBM 128
#define GBN 128
#define GBK 8

__global__ __launch_bounds__(256, 2)
void sgemm_bias(const float* __restrict__ A, const float* __restrict__ B,
                const float* __restrict__ bias, float* __restrict__ C,
                int M, int N, int K, int bmode, int relu)
{
    __shared__ float As[GBK][GBM];
    __shared__ float Bs[GBK][GBN];

    const int tid = threadIdx.x;
    const int bm  = blockIdx.y * GBM;
    const int bn  = blockIdx.x * GBN;
    const int tx  = tid & 15;
    const int ty  = tid >> 4;

    const int arow = tid >> 1;          // 0..127
    const int acol = (tid & 1) * 4;     // 0 or 4
    const int brow = tid >> 5;          // 0..7
    const int bcol = (tid & 31) * 4;    // 0..124

    const float* Aptr = A + (size_t)(bm + arow) * K + acol;

    float acc[8][8];
#pragma unroll
    for (int i = 0; i < 8; i++)
#pragma unroll
        for (int j = 0; j < 8; j++) acc[i][j] = 0.f;

    for (int k0 = 0; k0 < K; k0 += GBK) {
        // load A tile (128 x 8), stored transposed As[k][m]
        float4 av = *(const float4*)(Aptr + k0);
        As[acol + 0][arow] = av.x;
        As[acol + 1][arow] = av.y;
        As[acol + 2][arow] = av.z;
        As[acol + 3][arow] = av.w;

        // load B tile (8 x 128)
        {
            const int kk = k0 + brow;
            const int c  = bn + bcol;
            const float* bp;
            if (bmode == 0) bp = B + (size_t)kk * N + c;
            else            bp = B + ((size_t)(c >> 6) * K + kk) * 64 + (c & 63);
            float4 bv = *(const float4*)bp;
            *(float4*)&Bs[brow][bcol] = bv;
        }
        __syncthreads();

#pragma unroll
        for (int kk2 = 0; kk2 < GBK; kk2++) {
            float a[8], b[8];
            *(float4*)&a[0] = *(const float4*)&As[kk2][ty * 8];
            *(float4*)&a[4] = *(const float4*)&As[kk2][ty * 8 + 4];
            *(float4*)&b[0] = *(const float4*)&Bs[kk2][tx * 8];
            *(float4*)&b[4] = *(const float4*)&Bs[kk2][tx * 8 + 4];
#pragma unroll
            for (int i = 0; i < 8; i++)
#pragma unroll
                for (int j = 0; j < 8; j++)
                    acc[i][j] += a[i] * b[j];
        }
        __syncthreads();
    }

    // epilogue: bias (+ optional ReLU), float4 stores
#pragma unroll
    for (int i = 0; i < 8; i++) {
        const size_t row = (size_t)(bm + ty * 8 + i);
#pragma unroll
        for (int j = 0; j < 8; j += 4) {
            const int c = bn + tx * 8 + j;
            float4 v;
            v.x = acc[i][j + 0] + bias[c + 0];
            v.y = acc[i][j + 1] + bias[c + 1];
            v.z = acc[i][j + 2] + bias[c + 2];
            v.w = acc[i][j + 3] + bias[c + 3];
            if (relu) {
                v.x = fmaxf(v.x, 0.f); v.y = fmaxf(v.y, 0.f);
                v.z = fmaxf(v.z, 0.f); v.w = fmaxf(v.w, 0.f);
            }
            *(float4*)&C[row * N + c] = v;
        }
    }
}

// ---------------------------------------------------------------------------
// Fused flash-style attention.
// Q,K,V,O layouts: [token, h*64+e] (token = b*1024+s), i.e. row stride 1024.
// Grid: x = q-tile (S/64 = 16), y = b*H + h (64). Block: 256 threads.
// Online softmax over 16 K-tiles of 64. Q pre-scaled by 1/sqrt(64)=0.125.
// Dynamic smem: 4 * 64 * 68 floats = 69632 B.
// ---------------------------------------------------------------------------
#define APAD 68

extern __shared__ float attn_smem[];

__global__ __launch_bounds__(256)
void attention64(const float* __restrict__ Q, const float* __restrict__ K,
                 const float* __restrict__ V, float* __restrict__ O)
{
    float* Qt = attn_smem;              // [64][APAD]  Qt[e][r]  (transposed, scaled)
    float* Kt = Qt + 64 * APAD;         // [64][APAD]  Kt[e][c]  (transposed)
    float* Vs = Kt + 64 * APAD;         // [64][APAD]  Vs[j][e]  (natural)
    float* Ps = Vs + 64 * APAD;         // [64][APAD]  Ps[r][j]  (natural)

    const int tid = threadIdx.x;
    const int tx  = tid & 15;
    const int ty  = tid >> 4;
    const int bh  = blockIdx.y;
    const size_t base = (size_t)(bh >> 4) * (1024 * 1024) + (size_t)(bh & 15) * 64;
    const int q0 = blockIdx.x * 64;

    // ---- load Q tile transposed + scaled (coalesced global, 4-way smem scatter)
    {
        const int e  = tid & 63;
        const int r0 = tid >> 6;        // 0..3
#pragma unroll
        for (int t = 0; t < 16; t++) {
            const int r = r0 + t * 4;
            Qt[e * APAD + r] = Q[base + (size_t)(q0 + r) * 1024 + e] * 0.125f;
        }
    }

    float m[4], l[4], o[4][4];
#pragma unroll
    for (int i = 0; i < 4; i++) {
        m[i] = -CUDART_INF_F;
        l[i] = 0.f;
#pragma unroll
        for (int c = 0; c < 4; c++) o[i][c] = 0.f;
    }

    for (int kt = 0; kt < 16; kt++) {
        __syncthreads();   // previous PV readers done (also covers Qt at kt=0)

        // ---- load K (transposed) and V (natural) tiles
        {
            const int e  = tid & 63;
            const int r0 = tid >> 6;
#pragma unroll
            for (int t = 0; t < 16; t++) {
                const int r = r0 + t * 4;
                const size_t goff = base + (size_t)(kt * 64 + r) * 1024 + e;
                Kt[e * APAD + r] = K[goff];
                Vs[r * APAD + e] = V[goff];
            }
        }
        __syncthreads();

        // ---- scores S = (Q*0.125) @ K^T  : thread owns rows 4ty+i, cols 4tx+j
        float s[4][4];
#pragma unroll
        for (int i = 0; i < 4; i++)
#pragma unroll
            for (int j = 0; j < 4; j++) s[i][j] = 0.f;

#pragma unroll 8
        for (int e2 = 0; e2 < 64; e2++) {
            float qv[4], kv[4];
            *(float4*)qv = *(const float4*)&Qt[e2 * APAD + 4 * ty];
            *(float4*)kv = *(const float4*)&Kt[e2 * APAD + 4 * tx];
#pragma unroll
            for (int i = 0; i < 4; i++)
#pragma unroll
                for (int j = 0; j < 4; j++)
                    s[i][j] += qv[i] * kv[j];
        }

        // ---- online softmax update (row groups = 16 lanes sharing ty)
#pragma unroll
        for (int i = 0; i < 4; i++) {
            float rm = fmaxf(fmaxf(s[i][0], s[i][1]), fmaxf(s[i][2], s[i][3]));
#pragma unroll
            for (int off = 8; off >= 1; off >>= 1)
                rm = fmaxf(rm, __shfl_xor_sync(0xffffffffu, rm, off));

            const float mn   = fmaxf(m[i], rm);
            const float corr = __expf(m[i] - mn);
            const float p0 = __expf(s[i][0] - mn);
            const float p1 = __expf(s[i][1] - mn);
            const float p2 = __expf(s[i][2] - mn);
            const float p3 = __expf(s[i][3] - mn);

            float rs = p0 + p1 + p2 + p3;
#pragma unroll
            for (int off = 8; off >= 1; off >>= 1)
                rs += __shfl_xor_sync(0xffffffffu, rs, off);

            l[i] = l[i] * corr + rs;
            m[i] = mn;
#pragma unroll
            for (int c = 0; c < 4; c++) o[i][c] *= corr;

            float4 pv = make_float4(p0, p1, p2, p3);
            *(float4*)&Ps[(4 * ty + i) * APAD + 4 * tx] = pv;
        }
        __syncthreads();

        // ---- O += P @ V
#pragma unroll 8
        for (int j = 0; j < 64; j++) {
            float vv[4];
            *(float4*)vv = *(const float4*)&Vs[j * APAD + 4 * tx];
#pragma unroll
            for (int i = 0; i < 4; i++) {
                const float p = Ps[(4 * ty + i) * APAD + j];
#pragma unroll
                for (int c = 0; c < 4; c++) o[i][c] += p * vv[c];
            }
        }
    }

    // ---- finalize and store
#pragma unroll
    for (int i = 0; i < 4; i++) {
        const float inv = 1.f / l[i];
        const int r = q0 + 4 * ty + i;
        float4 v = make_float4(o[i][0] * inv, o[i][1] * inv,
                               o[i][2] * inv, o[i][3] * inv);
        *(float4*)&O[base + (size_t)r * 1024 + 4 * tx] = v;
    }
}

// ---------------------------------------------------------------------------
// Fused residual-add + LayerNorm over D=1024. Block per token, 256 threads.
// out = (x + r - mean) * rsqrt(var + 1e-5) * g + beta
// ---------------------------------------------------------------------------
__global__ __launch_bounds__(256)
void add_layernorm(const float* __restrict__ x, const float* __restrict__ r,
                   const float* __restrict__ g, const float* __restrict__ beta,
                   float* __restrict__ out)
{
    const int row = blockIdx.x;
    const int tid = threadIdx.x;
    const size_t off = (size_t)row * 1024 + tid * 4;

    float4 xv = *(const float4*)(x + off);
    float4 rv = *(const float4*)(r + off);
    float v0 = xv.x + rv.x, v1 = xv.y + rv.y, v2 = xv.z + rv.z, v3 = xv.w + rv.w;

    float s  = v0 + v1 + v2 + v3;
    float sq = v0 * v0 + v1 * v1 + v2 * v2 + v3 * v3;

#pragma unroll
    for (int o2 = 16; o2 >= 1; o2 >>= 1) {
        s  += __shfl_xor_sync(0xffffffffu, s,  o2);
        sq += __shfl_xor_sync(0xffffffffu, sq, o2);
    }

    __shared__ float ss[8], ssq[8];
    __shared__ float s_mean, s_rstd;
    const int warp = tid >> 5, lane = tid & 31;
    if (lane == 0) { ss[warp] = s; ssq[warp] = sq; }
    __syncthreads();
    if (tid < 32) {
        float a  = (tid < 8) ? ss[tid]  : 0.f;
        float aq = (tid < 8) ? ssq[tid] : 0.f;
#pragma unroll
        for (int o2 = 4; o2 >= 1; o2 >>= 1) {
            a  += __shfl_xor_sync(0xffffffffu, a,  o2);
            aq += __shfl_xor_sync(0xffffffffu, aq, o2);
        }
        if (tid == 0) {
            const float mean = a * (1.f / 1024.f);
            float var = aq * (1.f / 1024.f) - mean * mean;
            s_mean = mean;
            s_rstd = rsqrtf(var + 1e-5f);
        }
    }
    __syncthreads();

    const float mean = s_mean, rstd = s_rstd;
    float4 gv = *(const float4*)(g + tid * 4);
    float4 bv = *(const float4*)(beta + tid * 4);
    float4 ov;
    ov.x = (v0 - mean) * rstd * gv.x + bv.x;
    ov.y = (v1 - mean) * rstd * gv.y + bv.y;
    ov.z = (v2 - mean) * rstd * gv.z + bv.z;
    ov.w = (v3 - mean) * rstd * gv.w + bv.w;
    *(float4*)(out + off) = ov;
}

// ---------------------------------------------------------------------------
// kernel_launch
// Input order (metadata): query, modA, modB,
//   Wq1,bq1,Wk1,bk1,Wv1,bv1,Wo1,bo1, Wq2,bq2,Wk2,bk2,Wv2,bv2,Wo2,bo2,
//   W1,b1,W2,b2, g1,beta1,g2,beta2,g3,beta3
// ---------------------------------------------------------------------------
extern "C" void kernel_launch(void* const* d_in, const int* in_sizes, int n_in,
                              void* d_out, int out_size)
{
    const float* q_in = (const float*)d_in[0];
    const float* mA   = (const float*)d_in[1];
    const float* mB   = (const float*)d_in[2];
    const float* Wq1  = (const float*)d_in[3];
    const float* bq1  = (const float*)d_in[4];
    const float* Wk1  = (const float*)d_in[5];
    const float* bk1  = (const float*)d_in[6];
    const float* Wv1  = (const float*)d_in[7];
    const float* bv1  = (const float*)d_in[8];
    const float* Wo1  = (const float*)d_in[9];
    const float* bo1  = (const float*)d_in[10];
    const float* Wq2  = (const float*)d_in[11];
    const float* bq2  = (const float*)d_in[12];
    const float* Wk2  = (const float*)d_in[13];
    const float* bk2  = (const float*)d_in[14];
    const float* Wv2  = (const float*)d_in[15];
    const float* bv2  = (const float*)d_in[16];
    const float* Wo2  = (const float*)d_in[17];
    const float* bo2  = (const float*)d_in[18];
    const float* W1   = (const float*)d_in[19];
    const float* b1   = (const float*)d_in[20];
    const float* W2   = (const float*)d_in[21];
    const float* b2   = (const float*)d_in[22];
    const float* g1   = (const float*)d_in[23];
    const float* be1  = (const float*)d_in[24];
    const float* g2   = (const float*)d_in[25];
    const float* be2  = (const float*)d_in[26];
    const float* g3   = (const float*)d_in[27];
    const float* be3  = (const float*)d_in[28];

    float *Q, *K, *V, *ATT, *X1, *X2, *TMP, *HID;
    cudaGetSymbolAddress((void**)&Q,   g_Q);
    cudaGetSymbolAddress((void**)&K,   g_K);
    cudaGetSymbolAddress((void**)&V,   g_V);
    cudaGetSymbolAddress((void**)&ATT, g_att);
    cudaGetSymbolAddress((void**)&X1,  g_x1);
    cudaGetSymbolAddress((void**)&X2,  g_x2);
    cudaGetSymbolAddress((void**)&TMP, g_tmp);
    cudaGetSymbolAddress((void**)&HID, g_hid);

    cudaFuncSetAttribute(attention64,
                         cudaFuncAttributeMaxDynamicSharedMemorySize,
                         4 * 64 * APAD * (int)sizeof(float));

    const dim3 blk(256);
    const dim3 gProj(DMODEL / GBN, TOK / GBM);     // (8, 32)
    const dim3 gFF1 (HIDDEN / GBN, TOK / GBM);     // (32, 32)
    const dim3 gAttn(16, 64);
    const int  ASMEM = 4 * 64 * APAD * (int)sizeof(float);

    // ---- attention block 1 (Q from query, K/V from modality_A)
    sgemm_bias<<<gProj, blk>>>(q_in, Wq1, bq1, Q, TOK, DMODEL, DMODEL, 1, 0);
    sgemm_bias<<<gProj, blk>>>(mA,   Wk1, bk1, K, TOK, DMODEL, DMODEL, 1, 0);
    sgemm_bias<<<gProj, blk>>>(mA,   Wv1, bv1, V, TOK, DMODEL, DMODEL, 1, 0);
    attention64<<<gAttn, blk, ASMEM>>>(Q, K, V, ATT);
    sgemm_bias<<<gProj, blk>>>(ATT, Wo1, bo1, TMP, TOK, DMODEL, DMODEL, 0, 0);
    add_layernorm<<<TOK, blk>>>(q_in, TMP, g1, be1, X1);

    // ---- attention block 2 (Q from x1, K/V from modality_B)
    sgemm_bias<<<gProj, blk>>>(X1, Wq2, bq2, Q, TOK, DMODEL, DMODEL, 1, 0);
    sgemm_bias<<<gProj, blk>>>(mB, Wk2, bk2, K, TOK, DMODEL, DMODEL, 1, 0);
    sgemm_bias<<<gProj, blk>>>(mB, Wv2, bv2, V, TOK, DMODEL, DMODEL, 1, 0);
    attention64<<<gAttn, blk, ASMEM>>>(Q, K, V, ATT);
    sgemm_bias<<<gProj, blk>>>(ATT, Wo2, bo2, TMP, TOK, DMODEL, DMODEL, 0, 0);
    add_layernorm<<<TOK, blk>>>(X1, TMP, g2, be2, X2);

    // ---- feedforward
    sgemm_bias<<<gFF1,  blk>>>(X2,  W1, b1, HID, TOK, HIDDEN, DMODEL, 0, 1);
    sgemm_bias<<<gProj, blk>>>(HID, W2, b2, TMP, TOK, DMODEL, HIDDEN, 0, 0);
    add_layernorm<<<TOK, blk>>>(X2, TMP, g3, be3, (float*)d_out);
}

// round 3
// speedup vs baseline: 1.7695x; 1.7695x over previous
#include <cuda_runtime.h>
#include <cuda_fp16.h>
#include <math_constants.h>
#include <cstdint>

// ---------------------------------------------------------------------------
// Problem constants: B=4, S=1024, D=1024, H=16, DH=64, HID=4096
// ---------------------------------------------------------------------------
#define TOK    4096
#define DMODEL 1024
#define HIDDEN 4096

// ------------------------- scratch (__device__ globals) --------------------
__device__ float g_Q   [TOK * DMODEL];
__device__ float g_K   [TOK * DMODEL];
__device__ float g_V   [TOK * DMODEL];
__device__ float g_att [TOK * DMODEL];
__device__ float g_x1  [TOK * DMODEL];
__device__ float g_x2  [TOK * DMODEL];
__device__ float g_tmp [TOK * DMODEL];
__device__ float g_hid [(size_t)TOK * HIDDEN];

// ===========================================================================
// helpers
// ===========================================================================
__device__ __forceinline__ uint32_t smem_to_u32(const void* smem_ptr) {
    uint32_t addr;
    asm("{ .reg .u64 tmp; cvta.to.shared.u64 tmp, %1; cvt.u32.u64 %0, tmp; }"
        : "=r"(addr) : "l"(smem_ptr));
    return addr;
}

__device__ __forceinline__ void ldsm4(uint32_t* r, uint32_t a) {
    asm volatile("ldmatrix.sync.aligned.m8n8.x4.shared.b16 {%0,%1,%2,%3}, [%4];"
        : "=r"(r[0]), "=r"(r[1]), "=r"(r[2]), "=r"(r[3]) : "r"(a));
}
__device__ __forceinline__ void ldsm4t(uint32_t* r, uint32_t a) {
    asm volatile("ldmatrix.sync.aligned.m8n8.x4.trans.shared.b16 {%0,%1,%2,%3}, [%4];"
        : "=r"(r[0]), "=r"(r[1]), "=r"(r[2]), "=r"(r[3]) : "r"(a));
}
__device__ __forceinline__ void hmma(float* d, const uint32_t* a, const uint32_t* b) {
    asm volatile(
        "mma.sync.aligned.m16n8k16.row.col.f32.f16.f16.f32 "
        "{%0,%1,%2,%3}, {%4,%5,%6,%7}, {%8,%9}, {%0,%1,%2,%3};"
        : "+f"(d[0]), "+f"(d[1]), "+f"(d[2]), "+f"(d[3])
        : "r"(a[0]), "r"(a[1]), "r"(a[2]), "r"(a[3]), "r"(b[0]), "r"(b[1]));
}

// fp32 -> fp16 hi/lo split, packed as half2 words (lo half = first element)
__device__ __forceinline__ void split_pack4(const float4& v, uint32_t* hi, uint32_t* lo) {
    __half2 h0 = __floats2half2_rn(v.x, v.y);
    __half2 h1 = __floats2half2_rn(v.z, v.w);
    float2 f0 = __half22float2(h0);
    float2 f1 = __half22float2(h1);
    __half2 l0 = __floats2half2_rn(v.x - f0.x, v.y - f0.y);
    __half2 l1 = __floats2half2_rn(v.z - f1.x, v.w - f1.y);
    hi[0] = *(uint32_t*)&h0; hi[1] = *(uint32_t*)&h1;
    lo[0] = *(uint32_t*)&l0; lo[1] = *(uint32_t*)&l1;
}

// ===========================================================================
// HMMA GEMM: C[M,N] = A[M,K] @ B'[K,N] + bias[N]  (optional ReLU)
//   bmode 0: B row-major [K,N]; bmode 1: B per-head [H,K,64]
// 128x128 CTA tile, 8 warps (warp tile 32x64), K-chunk 32.
// fp16 hi/lo split: D = Ah*Bh + Ah*Bl + Al*Bh  (fp32 acc).
// smem per stage: Ahi/Alo [128][40] halves (80B rows, conflict-free ldmatrix),
//                 Bhi/Blo [32][128] halves (256B rows, SW128 chunk XOR).
// ===========================================================================
#define A_PART 10240                       // 128 * 80 B
#define B_PART 8192                        // 32 * 256 B
#define OFF_BHI (2 * A_PART)               // 20480
#define STAGE_BYTES (2 * A_PART + 2 * B_PART)   // 36864
#define GEMM_SMEM (2 * STAGE_BYTES)             // 73728

__global__ __launch_bounds__(256, 1)
void gemm_mma(const float* __restrict__ A, const float* __restrict__ B,
              const float* __restrict__ bias, float* __restrict__ C,
              int M, int N, int K, int bmode, int relu)
{
    extern __shared__ char smem[];
    const uint32_t sb0 = smem_to_u32(smem);
    const int tid  = threadIdx.x;
    const int lane = tid & 31;
    const int wid  = tid >> 5;
    const int bm   = blockIdx.y * 128;
    const int bn   = blockIdx.x * 128;
    const int wm   = (wid & 3) * 32;      // warp m-offset
    const int wn   = (wid >> 2) * 64;     // warp n-offset

    float acc[2][8][4];
#pragma unroll
    for (int f = 0; f < 2; ++f)
#pragma unroll
        for (int nf = 0; nf < 8; ++nf)
#pragma unroll
            for (int e = 0; e < 4; ++e) acc[f][nf][e] = 0.f;

    // per-thread global load mapping (64B contiguous per thread, coalesced)
    const int rA = tid >> 1, cA = (tid & 1) * 16;     // A: row, col-base
    const int kB = tid >> 3, cB = (tid & 7) * 16;     // B: k-row, n-base
    const float* Ag = A + (size_t)(bm + rA) * K + cA;
    const float* Bg;
    size_t BgStep;
    if (bmode == 0) { Bg = B + (size_t)kB * N + bn + cB;          BgStep = (size_t)32 * N; }
    else { const int c = bn + cB;
           Bg = B + ((size_t)(c >> 6) * K + kB) * 64 + (c & 63);  BgStep = 32 * 64; }

    const int NIT = K >> 5;
    float4 av[4], bv[4];

    for (int it = 0; it <= NIT; ++it) {
        // ---- prefetch next chunk's globals into registers
        if (it < NIT) {
            const float* ap = Ag + it * 32;
            const float* bp = Bg + (size_t)it * BgStep;
#pragma unroll
            for (int j = 0; j < 4; ++j) av[j] = *(const float4*)(ap + 4 * j);
#pragma unroll
            for (int j = 0; j < 4; ++j) bv[j] = *(const float4*)(bp + 4 * j);
        }

        // ---- compute on the previously-filled stage
        if (it > 0) {
            const uint32_t sbase = sb0 + (uint32_t)(((it - 1) & 1) * STAGE_BYTES);
#pragma unroll
            for (int ks = 0; ks < 2; ++ks) {
                uint32_t aH[2][4], aL[2][4], bH[4][4], bL[4][4];
#pragma unroll
                for (int f = 0; f < 2; ++f) {
                    const int m = wm + f * 16 + (lane & 15);
                    const uint32_t ad = sbase + (uint32_t)(m * 80 + (ks * 2 + (lane >> 4)) * 16);
                    ldsm4(aH[f], ad);
                    ldsm4(aL[f], ad + A_PART);
                }
#pragma unroll
                for (int p = 0; p < 4; ++p) {
                    const int k  = ks * 16 + (lane & 15);
                    const int nb = (wn >> 3) + p * 2 + (lane >> 4);
                    const uint32_t bd = sbase + OFF_BHI +
                        (uint32_t)(k * 256 + ((nb ^ (k & 7)) * 16));
                    ldsm4t(bH[p], bd);
                    ldsm4t(bL[p], bd + B_PART);
                }
#pragma unroll
                for (int f = 0; f < 2; ++f)
#pragma unroll
                    for (int p = 0; p < 4; ++p) {
                        hmma(acc[f][2 * p],     aH[f], &bH[p][0]);
                        hmma(acc[f][2 * p + 1], aH[f], &bH[p][2]);
                        hmma(acc[f][2 * p],     aH[f], &bL[p][0]);
                        hmma(acc[f][2 * p + 1], aH[f], &bL[p][2]);
                        hmma(acc[f][2 * p],     aL[f], &bH[p][0]);
                        hmma(acc[f][2 * p + 1], aL[f], &bH[p][2]);
                    }
            }
        }

        // ---- convert + store prefetched chunk into its stage
        if (it < NIT) {
            char* base = smem + (it & 1) * STAGE_BYTES;
#pragma unroll
            for (int j = 0; j < 4; ++j) {
                uint32_t hi[2], lo[2];
                split_pack4(av[j], hi, lo);
                char* ad = base + rA * 80 + cA * 2 + 8 * j;
                *(uint2*)(ad)          = make_uint2(hi[0], hi[1]);
                *(uint2*)(ad + A_PART) = make_uint2(lo[0], lo[1]);
            }
#pragma unroll
            for (int j = 0; j < 4; ++j) {
                uint32_t hi[2], lo[2];
                split_pack4(bv[j], hi, lo);
                const int n = cB + 4 * j;
                char* bd = base + OFF_BHI + kB * 256 +
                           ((n >> 3) ^ (kB & 7)) * 16 + (n & 7) * 2;
                *(uint2*)(bd)          = make_uint2(hi[0], hi[1]);
                *(uint2*)(bd + B_PART) = make_uint2(lo[0], lo[1]);
            }
            __syncthreads();
        }
    }

    // ---- epilogue: fused bias (+ReLU), float2 stores
    const int gr = lane >> 2, gc = (lane & 3) * 2;
#pragma unroll
    for (int f = 0; f < 2; ++f) {
        const int row0 = bm + wm + f * 16 + gr;
#pragma unroll
        for (int nf = 0; nf < 8; ++nf) {
            const int col = bn + wn + nf * 8 + gc;
            const float b0 = bias[col], b1 = bias[col + 1];
            float2 v0 = make_float2(acc[f][nf][0] + b0, acc[f][nf][1] + b1);
            float2 v1 = make_float2(acc[f][nf][2] + b0, acc[f][nf][3] + b1);
            if (relu) {
                v0.x = fmaxf(v0.x, 0.f); v0.y = fmaxf(v0.y, 0.f);
                v1.x = fmaxf(v1.x, 0.f); v1.y = fmaxf(v1.y, 0.f);
            }
            *(float2*)&C[(size_t)row0 * N + col]       = v0;
            *(float2*)&C[(size_t)(row0 + 8) * N + col] = v1;
        }
    }
}

// ===========================================================================
// Fused flash-style attention (unchanged from R1 baseline).
// ===========================================================================
#define APAD 68
extern __shared__ float attn_smem[];

__global__ __launch_bounds__(256)
void attention64(const float* __restrict__ Q, const float* __restrict__ K,
                 const float* __restrict__ V, float* __restrict__ O)
{
    float* Qt = attn_smem;
    float* Kt = Qt + 64 * APAD;
    float* Vs = Kt + 64 * APAD;
    float* Ps = Vs + 64 * APAD;

    const int tid = threadIdx.x;
    const int tx  = tid & 15;
    const int ty  = tid >> 4;
    const int bh  = blockIdx.y;
    const size_t base = (size_t)(bh >> 4) * (1024 * 1024) + (size_t)(bh & 15) * 64;
    const int q0 = blockIdx.x * 64;

    {
        const int e  = tid & 63;
        const int r0 = tid >> 6;
#pragma unroll
        for (int t = 0; t < 16; t++) {
            const int r = r0 + t * 4;
            Qt[e * APAD + r] = Q[base + (size_t)(q0 + r) * 1024 + e] * 0.125f;
        }
    }

    float m[4], l[4], o[4][4];
#pragma unroll
    for (int i = 0; i < 4; i++) {
        m[i] = -CUDART_INF_F;
        l[i] = 0.f;
#pragma unroll
        for (int c = 0; c < 4; c++) o[i][c] = 0.f;
    }

    for (int kt = 0; kt < 16; kt++) {
        __syncthreads();
        {
            const int e  = tid & 63;
            const int r0 = tid >> 6;
#pragma unroll
            for (int t = 0; t < 16; t++) {
                const int r = r0 + t * 4;
                const size_t goff = base + (size_t)(kt * 64 + r) * 1024 + e;
                Kt[e * APAD + r] = K[goff];
                Vs[r * APAD + e] = V[goff];
            }
        }
        __syncthreads();

        float s[4][4];
#pragma unroll
        for (int i = 0; i < 4; i++)
#pragma unroll
            for (int j = 0; j < 4; j++) s[i][j] = 0.f;

#pragma unroll 8
        for (int e2 = 0; e2 < 64; e2++) {
            float qv[4], kv[4];
            *(float4*)qv = *(const float4*)&Qt[e2 * APAD + 4 * ty];
            *(float4*)kv = *(const float4*)&Kt[e2 * APAD + 4 * tx];
#pragma unroll
            for (int i = 0; i < 4; i++)
#pragma unroll
                for (int j = 0; j < 4; j++)
                    s[i][j] += qv[i] * kv[j];
        }

#pragma unroll
        for (int i = 0; i < 4; i++) {
            float rm = fmaxf(fmaxf(s[i][0], s[i][1]), fmaxf(s[i][2], s[i][3]));
#pragma unroll
            for (int off = 8; off >= 1; off >>= 1)
                rm = fmaxf(rm, __shfl_xor_sync(0xffffffffu, rm, off));

            const float mn   = fmaxf(m[i], rm);
            const float corr = __expf(m[i] - mn);
            const float p0 = __expf(s[i][0] - mn);
            const float p1 = __expf(s[i][1] - mn);
            const float p2 = __expf(s[i][2] - mn);
            const float p3 = __expf(s[i][3] - mn);

            float rs = p0 + p1 + p2 + p3;
#pragma unroll
            for (int off = 8; off >= 1; off >>= 1)
                rs += __shfl_xor_sync(0xffffffffu, rs, off);

            l[i] = l[i] * corr + rs;
            m[i] = mn;
#pragma unroll
            for (int c = 0; c < 4; c++) o[i][c] *= corr;

            *(float4*)&Ps[(4 * ty + i) * APAD + 4 * tx] = make_float4(p0, p1, p2, p3);
        }
        __syncthreads();

#pragma unroll 8
        for (int j = 0; j < 64; j++) {
            float vv[4];
            *(float4*)vv = *(const float4*)&Vs[j * APAD + 4 * tx];
#pragma unroll
            for (int i = 0; i < 4; i++) {
                const float p = Ps[(4 * ty + i) * APAD + j];
#pragma unroll
                for (int c = 0; c < 4; c++) o[i][c] += p * vv[c];
            }
        }
    }

#pragma unroll
    for (int i = 0; i < 4; i++) {
        const float inv = 1.f / l[i];
        const int r = q0 + 4 * ty + i;
        *(float4*)&O[base + (size_t)r * 1024 + 4 * tx] =
            make_float4(o[i][0] * inv, o[i][1] * inv, o[i][2] * inv, o[i][3] * inv);
    }
}

// ===========================================================================
// Fused residual-add + LayerNorm (unchanged).
// ===========================================================================
__global__ __launch_bounds__(256)
void add_layernorm(const float* __restrict__ x, const float* __restrict__ r,
                   const float* __restrict__ g, const float* __restrict__ beta,
                   float* __restrict__ out)
{
    const int row = blockIdx.x;
    const int tid = threadIdx.x;
    const size_t off = (size_t)row * 1024 + tid * 4;

    float4 xv = *(const float4*)(x + off);
    float4 rv = *(const float4*)(r + off);
    float v0 = xv.x + rv.x, v1 = xv.y + rv.y, v2 = xv.z + rv.z, v3 = xv.w + rv.w;

    float s  = v0 + v1 + v2 + v3;
    float sq = v0 * v0 + v1 * v1 + v2 * v2 + v3 * v3;
#pragma unroll
    for (int o2 = 16; o2 >= 1; o2 >>= 1) {
        s  += __shfl_xor_sync(0xffffffffu, s,  o2);
        sq += __shfl_xor_sync(0xffffffffu, sq, o2);
    }

    __shared__ float ss[8], ssq[8];
    __shared__ float s_mean, s_rstd;
    const int warp = tid >> 5, lane = tid & 31;
    if (lane == 0) { ss[warp] = s; ssq[warp] = sq; }
    __syncthreads();
    if (tid < 32) {
        float a  = (tid < 8) ? ss[tid]  : 0.f;
        float aq = (tid < 8) ? ssq[tid] : 0.f;
#pragma unroll
        for (int o2 = 4; o2 >= 1; o2 >>= 1) {
            a  += __shfl_xor_sync(0xffffffffu, a,  o2);
            aq += __shfl_xor_sync(0xffffffffu, aq, o2);
        }
        if (tid == 0) {
            const float mean = a * (1.f / 1024.f);
            float var = aq * (1.f / 1024.f) - mean * mean;
            s_mean = mean;
            s_rstd = rsqrtf(var + 1e-5f);
        }
    }
    __syncthreads();

    const float mean = s_mean, rstd = s_rstd;
    float4 gv = *(const float4*)(g + tid * 4);
    float4 bv = *(const float4*)(beta + tid * 4);
    float4 ov;
    ov.x = (v0 - mean) * rstd * gv.x + bv.x;
    ov.y = (v1 - mean) * rstd * gv.y + bv.y;
    ov.z = (v2 - mean) * rstd * gv.z + bv.z;
    ov.w = (v3 - mean) * rstd * gv.w + bv.w;
    *(float4*)(out + off) = ov;
}

// ===========================================================================
// kernel_launch
// ===========================================================================
extern "C" void kernel_launch(void* const* d_in, const int* in_sizes, int n_in,
                              void* d_out, int out_size)
{
    const float* q_in = (const float*)d_in[0];
    const float* mA   = (const float*)d_in[1];
    const float* mB   = (const float*)d_in[2];
    const float* Wq1  = (const float*)d_in[3];
    const float* bq1  = (const float*)d_in[4];
    const float* Wk1  = (const float*)d_in[5];
    const float* bk1  = (const float*)d_in[6];
    const float* Wv1  = (const float*)d_in[7];
    const float* bv1  = (const float*)d_in[8];
    const float* Wo1  = (const float*)d_in[9];
    const float* bo1  = (const float*)d_in[10];
    const float* Wq2  = (const float*)d_in[11];
    const float* bq2  = (const float*)d_in[12];
    const float* Wk2  = (const float*)d_in[13];
    const float* bk2  = (const float*)d_in[14];
    const float* Wv2  = (const float*)d_in[15];
    const float* bv2  = (const float*)d_in[16];
    const float* Wo2  = (const float*)d_in[17];
    const float* bo2  = (const float*)d_in[18];
    const float* W1   = (const float*)d_in[19];
    const float* b1   = (const float*)d_in[20];
    const float* W2   = (const float*)d_in[21];
    const float* b2   = (const float*)d_in[22];
    const float* g1   = (const float*)d_in[23];
    const float* be1  = (const float*)d_in[24];
    const float* g2   = (const float*)d_in[25];
    const float* be2  = (const float*)d_in[26];
    const float* g3   = (const float*)d_in[27];
    const float* be3  = (const float*)d_in[28];

    float *Q, *K, *V, *ATT, *X1, *X2, *TMP, *HID;
    cudaGetSymbolAddress((void**)&Q,   g_Q);
    cudaGetSymbolAddress((void**)&K,   g_K);
    cudaGetSymbolAddress((void**)&V,   g_V);
    cudaGetSymbolAddress((void**)&ATT, g_att);
    cudaGetSymbolAddress((void**)&X1,  g_x1);
    cudaGetSymbolAddress((void**)&X2,  g_x2);
    cudaGetSymbolAddress((void**)&TMP, g_tmp);
    cudaGetSymbolAddress((void**)&HID, g_hid);

    cudaFuncSetAttribute(attention64,
                         cudaFuncAttributeMaxDynamicSharedMemorySize,
                         4 * 64 * APAD * (int)sizeof(float));
    cudaFuncSetAttribute(gemm_mma,
                         cudaFuncAttributeMaxDynamicSharedMemorySize, GEMM_SMEM);

    const dim3 blk(256);
    const dim3 gProj(DMODEL / 128, TOK / 128);     // (8, 32)
    const dim3 gFF1 (HIDDEN / 128, TOK / 128);     // (32, 32)
    const dim3 gAttn(16, 64);
    const int  ASMEM = 4 * 64 * APAD * (int)sizeof(float);

    // ---- attention block 1 (Q from query, K/V from modality_A)
    gemm_mma<<<gProj, blk, GEMM_SMEM>>>(q_in, Wq1, bq1, Q, TOK, DMODEL, DMODEL, 1, 0);
    gemm_mma<<<gProj, blk, GEMM_SMEM>>>(mA,   Wk1, bk1, K, TOK, DMODEL, DMODEL, 1, 0);
    gemm_mma<<<gProj, blk, GEMM_SMEM>>>(mA,   Wv1, bv1, V, TOK, DMODEL, DMODEL, 1, 0);
    attention64<<<gAttn, blk, ASMEM>>>(Q, K, V, ATT);
    gemm_mma<<<gProj, blk, GEMM_SMEM>>>(ATT, Wo1, bo1, TMP, TOK, DMODEL, DMODEL, 0, 0);
    add_layernorm<<<TOK, blk>>>(q_in, TMP, g1, be1, X1);

    // ---- attention block 2 (Q from x1, K/V from modality_B)
    gemm_mma<<<gProj, blk, GEMM_SMEM>>>(X1, Wq2, bq2, Q, TOK, DMODEL, DMODEL, 1, 0);
    gemm_mma<<<gProj, blk, GEMM_SMEM>>>(mB, Wk2, bk2, K, TOK, DMODEL, DMODEL, 1, 0);
    gemm_mma<<<gProj, blk, GEMM_SMEM>>>(mB, Wv2, bv2, V, TOK, DMODEL, DMODEL, 1, 0);
    attention64<<<gAttn, blk, ASMEM>>>(Q, K, V, ATT);
    gemm_mma<<<gProj, blk, GEMM_SMEM>>>(ATT, Wo2, bo2, TMP, TOK, DMODEL, DMODEL, 0, 0);
    add_layernorm<<<TOK, blk>>>(X1, TMP, g2, be2, X2);

    // ---- feedforward
    gemm_mma<<<gFF1,  blk, GEMM_SMEM>>>(X2,  W1, b1, HID, TOK, HIDDEN, DMODEL, 0, 1);
    gemm_mma<<<gProj, blk, GEMM_SMEM>>>(HID, W2, b2, TMP, TOK, DMODEL, HIDDEN, 0, 0);
    add_layernorm<<<TOK, blk>>>(X2, TMP, g3, be3, (float*)d_out);
}